// round 1
// baseline (speedup 1.0000x reference)
#include <cuda_runtime.h>
#include <cstdint>

// Problem constants (fixed by the reference)
#define BB    2
#define SEQ   2048
#define HID   2048
#define NHEAD 16
#define DHEAD 128
#define MTOT  (BB * SEQ)      // 4096
#define NQKV  (3 * HID)       // 6144

// ---------------------------------------------------------------------------
// Device scratch (static __device__ arrays: allocation-guard safe)
// ---------------------------------------------------------------------------
__device__ float g_q[(size_t)BB * NHEAD * SEQ * DHEAD];     // [b,h,s,d]
__device__ float g_k[(size_t)BB * NHEAD * SEQ * DHEAD];
__device__ float g_v[(size_t)BB * NHEAD * SEQ * DHEAD];
__device__ float g_attn[(size_t)MTOT * HID];                // [b*s, h*d]

// ---------------------------------------------------------------------------
// tf32 helpers: 3xTF32 error-compensated MMA building blocks
// ---------------------------------------------------------------------------
__device__ __forceinline__ uint32_t f2tf(float x) {
    uint32_t r;
    asm("cvt.rna.tf32.f32 %0, %1;" : "=r"(r) : "f"(x));
    return r;
}
__device__ __forceinline__ void split_tf(float x, uint32_t &hi, uint32_t &lo) {
    hi = f2tf(x);
    lo = f2tf(x - __uint_as_float(hi));
}
__device__ __forceinline__ void mma8(float *d,
                                     uint32_t a0, uint32_t a1, uint32_t a2, uint32_t a3,
                                     uint32_t b0, uint32_t b1) {
    asm volatile(
        "mma.sync.aligned.m16n8k8.row.col.f32.tf32.tf32.f32 "
        "{%0,%1,%2,%3}, {%4,%5,%6,%7}, {%8,%9}, {%0,%1,%2,%3};\n"
        : "+f"(d[0]), "+f"(d[1]), "+f"(d[2]), "+f"(d[3])
        : "r"(a0), "r"(a1), "r"(a2), "r"(a3), "r"(b0), "r"(b1));
}

// ---------------------------------------------------------------------------
// GEMM: C[M,N] = A[M,K] @ B[K,N] + bias, 3xTF32.
// Block tile 128x128, K-step 32. 256 threads = 8 warps (4 M x 2 N),
// warp tile 32x64 = 2 m16 tiles x 8 n8 tiles.
// MODE 0: plain row-major output to Cout
// MODE 1: QKV scatter into g_q/g_k/g_v ([b,h,s,d])
// MODE 2: A comes from g_attn, plain output to Cout
// ---------------------------------------------------------------------------
template <int MODE>
__global__ void __launch_bounds__(256, 1)
gemm_tf32x3(const float *__restrict__ Ain, const float *__restrict__ Bw,
            const float *__restrict__ bias, float *__restrict__ Cout,
            int M, int N, int K) {
    __shared__ float Asm[128 * 36];   // 128 rows x 32 k, stride 36 (pad, f4-aligned)
    __shared__ float Bsm[32 * 132];   // 32 k x 128 n, stride 132

    const float *A = (MODE == 2) ? g_attn : Ain;

    const int tid  = threadIdx.x;
    const int lane = tid & 31;
    const int warp = tid >> 5;
    const int wm   = warp & 3;
    const int wn   = warp >> 2;
    const int m0   = blockIdx.y * 128;
    const int n0   = blockIdx.x * 128;
    const int g    = lane >> 2;   // 0..7
    const int q4   = lane & 3;    // 0..3

    float acc[2][8][4];
#pragma unroll
    for (int i = 0; i < 2; i++)
#pragma unroll
        for (int j = 0; j < 8; j++)
#pragma unroll
            for (int e = 0; e < 4; e++) acc[i][j][e] = 0.f;

    for (int kb = 0; kb < K; kb += 32) {
        // Load A tile: 128x32 floats = 1024 float4 slots
#pragma unroll
        for (int i = 0; i < 4; i++) {
            int s   = tid + i * 256;
            int row = s >> 3;
            int kq  = (s & 7) << 2;
            float4 fv = *(const float4 *)(A + (size_t)(m0 + row) * K + kb + kq);
            *(float4 *)(Asm + row * 36 + kq) = fv;
        }
        // Load B tile: 32x128 floats = 1024 float4 slots
#pragma unroll
        for (int i = 0; i < 4; i++) {
            int s   = tid + i * 256;
            int row = s >> 5;
            int nq  = (s & 31) << 2;
            float4 fv = *(const float4 *)(Bw + (size_t)(kb + row) * N + n0 + nq);
            *(float4 *)(Bsm + row * 132 + nq) = fv;
        }
        __syncthreads();

#pragma unroll
        for (int kk = 0; kk < 4; kk++) {
            const int k8 = kk * 8;
            uint32_t ah[2][4], al[2][4];
#pragma unroll
            for (int mt = 0; mt < 2; mt++) {
                int r = wm * 32 + mt * 16 + g;
                int c = k8 + q4;
                split_tf(Asm[r * 36 + c],           ah[mt][0], al[mt][0]);
                split_tf(Asm[(r + 8) * 36 + c],     ah[mt][1], al[mt][1]);
                split_tf(Asm[r * 36 + c + 4],       ah[mt][2], al[mt][2]);
                split_tf(Asm[(r + 8) * 36 + c + 4], ah[mt][3], al[mt][3]);
            }
#pragma unroll
            for (int nt = 0; nt < 8; nt++) {
                int col = wn * 64 + nt * 8 + g;
                int kr  = k8 + q4;
                uint32_t bh0, bl0, bh1, bl1;
                split_tf(Bsm[kr * 132 + col],       bh0, bl0);
                split_tf(Bsm[(kr + 4) * 132 + col], bh1, bl1);
#pragma unroll
                for (int mt = 0; mt < 2; mt++) {
                    mma8(acc[mt][nt], ah[mt][0], ah[mt][1], ah[mt][2], ah[mt][3], bh0, bh1);
                    mma8(acc[mt][nt], ah[mt][0], ah[mt][1], ah[mt][2], ah[mt][3], bl0, bl1);
                    mma8(acc[mt][nt], al[mt][0], al[mt][1], al[mt][2], al[mt][3], bh0, bh1);
                }
            }
        }
        __syncthreads();
    }

    // Epilogue
#pragma unroll
    for (int mt = 0; mt < 2; mt++) {
#pragma unroll
        for (int nt = 0; nt < 8; nt++) {
            int row = m0 + wm * 32 + mt * 16 + g;
            int col = n0 + wn * 64 + nt * 8 + (q4 << 1);
            float b0 = bias[col];
            float b1 = bias[col + 1];
            float2 v0 = make_float2(acc[mt][nt][0] + b0, acc[mt][nt][1] + b1);
            float2 v1 = make_float2(acc[mt][nt][2] + b0, acc[mt][nt][3] + b1);
            if (MODE == 1) {
                int which = col / HID;
                int hn    = col % HID;
                int head  = hn / DHEAD;
                int dc    = hn % DHEAD;
                float *dst = (which == 0) ? g_q : ((which == 1) ? g_k : g_v);
                int bi = row / SEQ;
                int si = row % SEQ;   // row+8 stays in same batch (128-aligned tiles)
                size_t base = ((size_t)(bi * NHEAD + head) * SEQ + si) * DHEAD + dc;
                *(float2 *)(dst + base) = v0;
                *(float2 *)(dst + base + (size_t)8 * DHEAD) = v1;
            } else {
                *(float2 *)(Cout + (size_t)row * N + col) = v0;
                *(float2 *)(Cout + (size_t)(row + 8) * N + col) = v1;
            }
        }
    }
}

// ---------------------------------------------------------------------------
// Flash attention (causal), 3xTF32 on tensor pipe.
// CTA: 128 Q rows, 8 warps (16 rows each). KV tile = 64 rows. d = 128.
// Streaming softmax (FA2). Output -> g_attn [b*s, h*128+dc].
// ---------------------------------------------------------------------------
#define FLASH_SMEM ((128 * 132 + 64 * 132 + 64 * 132 + 128 * 65) * 4)

__global__ void __launch_bounds__(256, 1) flash_causal() {
    extern __shared__ float sm[];
    float *Qsm = sm;                    // 128 x 132 (stride-padded)
    float *Ksm = Qsm + 128 * 132;       // 64 x 132
    float *Vsm = Ksm + 64 * 132;        // 64 x 132
    float *Psm = Vsm + 64 * 132;        // 128 x 65

    const int qt   = blockIdx.x;        // 0..15
    const int h    = blockIdx.y;        // 0..15
    const int b    = blockIdx.z;        // 0..1
    const int tid  = threadIdx.x;
    const int lane = tid & 31;
    const int warp = tid >> 5;
    const int g    = lane >> 2;
    const int q4   = lane & 3;

    const size_t headoff = (size_t)(b * NHEAD + h) * SEQ * DHEAD;
    const float *Qg = g_q + headoff;
    const float *Kg = g_k + headoff;
    const float *Vg = g_v + headoff;

    const int   qr0   = qt * 128;
    const float scale = 0.088388347648318447f;  // 128^-0.5

    // Load Q tile (scaled): 128 x 128 floats = 4096 float4 slots
    for (int i = tid; i < 128 * 32; i += 256) {
        int row = i >> 5;
        int cq  = (i & 31) << 2;
        float4 fv = *(const float4 *)(Qg + (size_t)(qr0 + row) * DHEAD + cq);
        fv.x *= scale; fv.y *= scale; fv.z *= scale; fv.w *= scale;
        *(float4 *)(Qsm + row * 132 + cq) = fv;
    }

    float Oacc[16][4];
#pragma unroll
    for (int i = 0; i < 16; i++)
#pragma unroll
        for (int e = 0; e < 4; e++) Oacc[i][e] = 0.f;
    float m_i[2] = {-1e30f, -1e30f};
    float l_i[2] = {0.f, 0.f};

    const int wr0   = warp * 16;
    const int grow0 = qr0 + wr0;
    const int jmax  = 2 * qt + 1;

    for (int j = 0; j <= jmax; j++) {
        const int kv0 = j * 64;
        __syncthreads();   // prior iter done reading Ksm/Vsm (covers Q load on j=0 via next sync)
        for (int i = tid; i < 64 * 32; i += 256) {
            int row = i >> 5;
            int cq  = (i & 31) << 2;
            *(float4 *)(Ksm + row * 132 + cq) =
                *(const float4 *)(Kg + (size_t)(kv0 + row) * DHEAD + cq);
            *(float4 *)(Vsm + row * 132 + cq) =
                *(const float4 *)(Vg + (size_t)(kv0 + row) * DHEAD + cq);
        }
        __syncthreads();

        if (kv0 <= grow0 + 15) {   // warp has at least one unmasked column
            // ---- S = (Q*scale) @ K^T : 16 x 64 per warp ----
            float sacc[8][4];
#pragma unroll
            for (int nt = 0; nt < 8; nt++)
#pragma unroll
                for (int e = 0; e < 4; e++) sacc[nt][e] = 0.f;

#pragma unroll
            for (int kk = 0; kk < 16; kk++) {
                const int k8 = kk * 8;
                const int r  = wr0 + g;
                const int c  = k8 + q4;
                uint32_t ah[4], al[4];
                split_tf(Qsm[r * 132 + c],           ah[0], al[0]);
                split_tf(Qsm[(r + 8) * 132 + c],     ah[1], al[1]);
                split_tf(Qsm[r * 132 + c + 4],       ah[2], al[2]);
                split_tf(Qsm[(r + 8) * 132 + c + 4], ah[3], al[3]);
#pragma unroll
                for (int nt = 0; nt < 8; nt++) {
                    int n = nt * 8 + g;
                    uint32_t bh0, bl0, bh1, bl1;
                    split_tf(Ksm[n * 132 + k8 + q4],     bh0, bl0);  // B[k][n] = K[n][k]
                    split_tf(Ksm[n * 132 + k8 + q4 + 4], bh1, bl1);
                    mma8(sacc[nt], ah[0], ah[1], ah[2], ah[3], bh0, bh1);
                    mma8(sacc[nt], ah[0], ah[1], ah[2], ah[3], bl0, bl1);
                    mma8(sacc[nt], al[0], al[1], al[2], al[3], bh0, bh1);
                }
            }

            // ---- causal mask (only near diagonal) ----
            if (kv0 + 63 > grow0) {
                const int r0 = grow0 + g;
#pragma unroll
                for (int nt = 0; nt < 8; nt++) {
                    int c0 = kv0 + nt * 8 + (q4 << 1);
                    if (c0 > r0)         sacc[nt][0] = -1e30f;
                    if (c0 + 1 > r0)     sacc[nt][1] = -1e30f;
                    if (c0 > r0 + 8)     sacc[nt][2] = -1e30f;
                    if (c0 + 1 > r0 + 8) sacc[nt][3] = -1e30f;
                }
            }

            // ---- streaming softmax ----
            float rmax0 = -1e30f, rmax1 = -1e30f;
#pragma unroll
            for (int nt = 0; nt < 8; nt++) {
                rmax0 = fmaxf(rmax0, fmaxf(sacc[nt][0], sacc[nt][1]));
                rmax1 = fmaxf(rmax1, fmaxf(sacc[nt][2], sacc[nt][3]));
            }
            rmax0 = fmaxf(rmax0, __shfl_xor_sync(0xffffffffu, rmax0, 1));
            rmax0 = fmaxf(rmax0, __shfl_xor_sync(0xffffffffu, rmax0, 2));
            rmax1 = fmaxf(rmax1, __shfl_xor_sync(0xffffffffu, rmax1, 1));
            rmax1 = fmaxf(rmax1, __shfl_xor_sync(0xffffffffu, rmax1, 2));

            float mn0 = fmaxf(m_i[0], rmax0);
            float mn1 = fmaxf(m_i[1], rmax1);
            float alpha0 = __expf(m_i[0] - mn0);
            float alpha1 = __expf(m_i[1] - mn1);

            float rs0 = 0.f, rs1 = 0.f;
#pragma unroll
            for (int nt = 0; nt < 8; nt++) {
                sacc[nt][0] = __expf(sacc[nt][0] - mn0);
                sacc[nt][1] = __expf(sacc[nt][1] - mn0);
                sacc[nt][2] = __expf(sacc[nt][2] - mn1);
                sacc[nt][3] = __expf(sacc[nt][3] - mn1);
                rs0 += sacc[nt][0] + sacc[nt][1];
                rs1 += sacc[nt][2] + sacc[nt][3];
            }
            rs0 += __shfl_xor_sync(0xffffffffu, rs0, 1);
            rs0 += __shfl_xor_sync(0xffffffffu, rs0, 2);
            rs1 += __shfl_xor_sync(0xffffffffu, rs1, 1);
            rs1 += __shfl_xor_sync(0xffffffffu, rs1, 2);

            l_i[0] = l_i[0] * alpha0 + rs0;
            l_i[1] = l_i[1] * alpha1 + rs1;
            m_i[0] = mn0;
            m_i[1] = mn1;

#pragma unroll
            for (int nt = 0; nt < 16; nt++) {
                Oacc[nt][0] *= alpha0; Oacc[nt][1] *= alpha0;
                Oacc[nt][2] *= alpha1; Oacc[nt][3] *= alpha1;
            }

            // ---- P -> smem (warp-private region), then O += P @ V ----
            const int pr = wr0 + g;
#pragma unroll
            for (int nt = 0; nt < 8; nt++) {
                int pc = nt * 8 + (q4 << 1);
                Psm[pr * 65 + pc]           = sacc[nt][0];
                Psm[pr * 65 + pc + 1]       = sacc[nt][1];
                Psm[(pr + 8) * 65 + pc]     = sacc[nt][2];
                Psm[(pr + 8) * 65 + pc + 1] = sacc[nt][3];
            }
            __syncwarp();

#pragma unroll
            for (int kk = 0; kk < 8; kk++) {
                const int k8 = kk * 8;
                const int r  = wr0 + g;
                const int c  = k8 + q4;
                uint32_t ah[4], al[4];
                split_tf(Psm[r * 65 + c],           ah[0], al[0]);
                split_tf(Psm[(r + 8) * 65 + c],     ah[1], al[1]);
                split_tf(Psm[r * 65 + c + 4],       ah[2], al[2]);
                split_tf(Psm[(r + 8) * 65 + c + 4], ah[3], al[3]);
#pragma unroll
                for (int nt = 0; nt < 16; nt++) {
                    int n = nt * 8 + g;
                    uint32_t bh0, bl0, bh1, bl1;
                    split_tf(Vsm[(k8 + q4) * 132 + n],     bh0, bl0);  // B[k][n] = V[k][n]
                    split_tf(Vsm[(k8 + q4 + 4) * 132 + n], bh1, bl1);
                    mma8(Oacc[nt], ah[0], ah[1], ah[2], ah[3], bh0, bh1);
                    mma8(Oacc[nt], ah[0], ah[1], ah[2], ah[3], bl0, bl1);
                    mma8(Oacc[nt], al[0], al[1], al[2], al[3], bh0, bh1);
                }
            }
            __syncwarp();   // P reads done before next iteration overwrites Psm
        }
    }

    // ---- epilogue: normalize and write attn output ----
    const float inv0 = 1.f / l_i[0];
    const float inv1 = 1.f / l_i[1];
    const int   s0   = qr0 + wr0 + g;
    const size_t rowbase0 = ((size_t)(b * SEQ) + s0) * HID + h * DHEAD;
    const size_t rowbase1 = rowbase0 + (size_t)8 * HID;
#pragma unroll
    for (int nt = 0; nt < 16; nt++) {
        int col = nt * 8 + (q4 << 1);
        float2 v0 = make_float2(Oacc[nt][0] * inv0, Oacc[nt][1] * inv0);
        float2 v1 = make_float2(Oacc[nt][2] * inv1, Oacc[nt][3] * inv1);
        *(float2 *)(g_attn + rowbase0 + col) = v0;
        *(float2 *)(g_attn + rowbase1 + col) = v1;
    }
}

// ---------------------------------------------------------------------------
// kernel_launch
// Inputs (metadata order): hidden_states, w_attn, b_attn, w_proj, b_proj
// ---------------------------------------------------------------------------
extern "C" void kernel_launch(void *const *d_in, const int *in_sizes, int n_in,
                              void *d_out, int out_size) {
    (void)in_sizes; (void)n_in; (void)out_size;
    const float *hs     = (const float *)d_in[0];
    const float *w_attn = (const float *)d_in[1];
    const float *b_attn = (const float *)d_in[2];
    const float *w_proj = (const float *)d_in[3];
    const float *b_proj = (const float *)d_in[4];
    float *out = (float *)d_out;

    cudaFuncSetAttribute(flash_causal,
                         cudaFuncAttributeMaxDynamicSharedMemorySize, FLASH_SMEM);

    // 1) QKV projection -> g_q/g_k/g_v
    gemm_tf32x3<1><<<dim3(NQKV / 128, MTOT / 128), 256>>>(
        hs, w_attn, b_attn, nullptr, MTOT, NQKV, HID);

    // 2) causal flash attention -> g_attn
    flash_causal<<<dim3(SEQ / 128, NHEAD, BB), 256, FLASH_SMEM>>>();

    // 3) output projection -> d_out
    gemm_tf32x3<2><<<dim3(HID / 128, MTOT / 128), 256>>>(
        nullptr, w_proj, b_proj, out, MTOT, HID, HID);
}

// round 2
// speedup vs baseline: 1.3398x; 1.3398x over previous
#include <cuda_runtime.h>
#include <cstdint>

// Problem constants (fixed by the reference)
#define BB    2
#define SEQ   2048
#define HID   2048
#define NHEAD 16
#define DHEAD 128
#define MTOT  (BB * SEQ)      // 4096
#define NQKV  (3 * HID)       // 6144

// ---------------------------------------------------------------------------
// Device scratch (static __device__ arrays: allocation-guard safe)
// ---------------------------------------------------------------------------
__device__ float g_q[(size_t)BB * NHEAD * SEQ * DHEAD];     // [b,h,s,d]
__device__ float g_k[(size_t)BB * NHEAD * SEQ * DHEAD];
__device__ float g_v[(size_t)BB * NHEAD * SEQ * DHEAD];
__device__ float g_attn[(size_t)MTOT * HID];                // [b*s, h*d]

// ---------------------------------------------------------------------------
// bf16x3 helpers
// ---------------------------------------------------------------------------
// Split (x0, x1) into packed bf16 pairs: h = {bf16(x0) lo16, bf16(x1) hi16},
// l = same for the fp32 residuals. Residual subtraction is exact (Sterbenz).
__device__ __forceinline__ void split_pack(float x0, float x1,
                                           uint32_t &h, uint32_t &l) {
    asm("cvt.rn.bf16x2.f32 %0, %1, %2;" : "=r"(h) : "f"(x1), "f"(x0));
    float h0 = __uint_as_float(h << 16);
    float h1 = __uint_as_float(h & 0xffff0000u);
    asm("cvt.rn.bf16x2.f32 %0, %1, %2;" : "=r"(l) : "f"(x1 - h1), "f"(x0 - h0));
}

__device__ __forceinline__ void mma16(float *d,
                                      uint32_t a0, uint32_t a1, uint32_t a2, uint32_t a3,
                                      uint32_t b0, uint32_t b1) {
    asm volatile(
        "mma.sync.aligned.m16n8k16.row.col.f32.bf16.bf16.f32 "
        "{%0,%1,%2,%3}, {%4,%5,%6,%7}, {%8,%9}, {%0,%1,%2,%3};\n"
        : "+f"(d[0]), "+f"(d[1]), "+f"(d[2]), "+f"(d[3])
        : "r"(a0), "r"(a1), "r"(a2), "r"(a3), "r"(b0), "r"(b1));
}

// 3-term error-compensated product-accumulate
__device__ __forceinline__ void mma3(float *d, const uint32_t *ah, const uint32_t *al,
                                     uint32_t bh0, uint32_t bh1,
                                     uint32_t bl0, uint32_t bl1) {
    mma16(d, ah[0], ah[1], ah[2], ah[3], bh0, bh1);
    mma16(d, ah[0], ah[1], ah[2], ah[3], bl0, bl1);
    mma16(d, al[0], al[1], al[2], al[3], bh0, bh1);
}

// ---------------------------------------------------------------------------
// GEMM: C[M,N] = A[M,K] @ B[K,N] + bias, bf16x3, double-buffered smem.
// Block tile 128x128, K-step 32. 256 threads = 8 warps (4 M x 2 N),
// warp tile 32x64 = 2 m16 x 8 n8.
// smem (u32): per stage [Ahi 128x20][Alo][Bhi 128x20][Blo] = 10240; x2 stages.
// MODE 1: QKV scatter into g_q/g_k/g_v  |  MODE 2: A = g_attn
// ---------------------------------------------------------------------------
#define GEMM_SMEM (2 * 10240 * 4)

template <int MODE>
__global__ void __launch_bounds__(256)
gemm_bf16x3(const float *__restrict__ Ain, const float *__restrict__ Bw,
            const float *__restrict__ bias, float *__restrict__ Cout,
            int M, int N, int K) {
    extern __shared__ uint32_t smg[];
    const float *A = (MODE == 2) ? g_attn : Ain;

    const int tid  = threadIdx.x;
    const int lane = tid & 31;
    const int warp = tid >> 5;
    const int wm   = warp & 3;
    const int wn   = warp >> 2;
    const int m0   = blockIdx.y * 128;
    const int n0   = blockIdx.x * 128;
    const int g    = lane >> 2;
    const int q4   = lane & 3;

    float acc[2][8][4];
#pragma unroll
    for (int i = 0; i < 2; i++)
#pragma unroll
        for (int j = 0; j < 8; j++)
#pragma unroll
            for (int e = 0; e < 4; e++) acc[i][j][e] = 0.f;

    float4 areg[4];
    float4 breg[2][2];

    auto load_regs = [&](int kb) {
#pragma unroll
        for (int i = 0; i < 4; i++) {
            int s = tid + i * 256;
            int row = s >> 3;
            int kq = (s & 7) << 2;
            areg[i] = *(const float4 *)(A + (size_t)(m0 + row) * K + kb + kq);
        }
#pragma unroll
        for (int i = 0; i < 2; i++) {
            int s  = tid + i * 256;
            int kp = s >> 5;
            int c4 = s & 31;
            const float *bp = Bw + (size_t)(kb + 2 * kp) * N + n0 + 4 * c4;
            breg[i][0] = *(const float4 *)bp;
            breg[i][1] = *(const float4 *)(bp + N);
        }
    };

    auto store_stage = [&](int st) {
        uint32_t *Ah = smg + st * 10240;
        uint32_t *Al = Ah + 2560;
        uint32_t *Bh = Ah + 5120;
        uint32_t *Bl = Ah + 7680;
#pragma unroll
        for (int i = 0; i < 4; i++) {
            int s = tid + i * 256;
            int row = s >> 3;
            int kq = (s & 7) << 2;
            uint32_t h0, l0, h1, l1;
            split_pack(areg[i].x, areg[i].y, h0, l0);
            split_pack(areg[i].z, areg[i].w, h1, l1);
            int o = row * 20 + (kq >> 1);
            Ah[o] = h0; Ah[o + 1] = h1;
            Al[o] = l0; Al[o + 1] = l1;
        }
#pragma unroll
        for (int i = 0; i < 2; i++) {
            int s  = tid + i * 256;
            int kp = s >> 5;
            int n  = (s & 31) * 4;
            const float *r0 = (const float *)&breg[i][0];
            const float *r1 = (const float *)&breg[i][1];
#pragma unroll
            for (int j = 0; j < 4; j++) {
                uint32_t h, l;
                split_pack(r0[j], r1[j], h, l);
                Bh[(n + j) * 20 + kp] = h;
                Bl[(n + j) * 20 + kp] = l;
            }
        }
    };

    auto compute = [&](int st) {
        const uint32_t *Ah = smg + st * 10240;
        const uint32_t *Al = Ah + 2560;
        const uint32_t *Bh = Ah + 5120;
        const uint32_t *Bl = Ah + 7680;
#pragma unroll
        for (int kk = 0; kk < 2; kk++) {
            const int kp0 = kk * 8 + q4;
            uint32_t ah[2][4], al[2][4];
#pragma unroll
            for (int mt = 0; mt < 2; mt++) {
                int r = wm * 32 + mt * 16 + g;
                ah[mt][0] = Ah[r * 20 + kp0];
                ah[mt][1] = Ah[(r + 8) * 20 + kp0];
                ah[mt][2] = Ah[r * 20 + kp0 + 4];
                ah[mt][3] = Ah[(r + 8) * 20 + kp0 + 4];
                al[mt][0] = Al[r * 20 + kp0];
                al[mt][1] = Al[(r + 8) * 20 + kp0];
                al[mt][2] = Al[r * 20 + kp0 + 4];
                al[mt][3] = Al[(r + 8) * 20 + kp0 + 4];
            }
#pragma unroll
            for (int nt = 0; nt < 8; nt++) {
                int n = wn * 64 + nt * 8 + g;
                uint32_t bh0 = Bh[n * 20 + kp0];
                uint32_t bh1 = Bh[n * 20 + kp0 + 4];
                uint32_t bl0 = Bl[n * 20 + kp0];
                uint32_t bl1 = Bl[n * 20 + kp0 + 4];
#pragma unroll
                for (int mt = 0; mt < 2; mt++)
                    mma3(acc[mt][nt], ah[mt], al[mt], bh0, bh1, bl0, bl1);
            }
        }
    };

    const int nIter = K >> 5;
    load_regs(0);
    store_stage(0);
    __syncthreads();
    for (int it = 0; it < nIter; ++it) {
        if (it + 1 < nIter) load_regs((it + 1) << 5);
        compute(it & 1);
        if (it + 1 < nIter) {
            store_stage((it + 1) & 1);
            __syncthreads();
        }
    }

    // Epilogue
#pragma unroll
    for (int mt = 0; mt < 2; mt++) {
#pragma unroll
        for (int nt = 0; nt < 8; nt++) {
            int row = m0 + wm * 32 + mt * 16 + g;
            int col = n0 + wn * 64 + nt * 8 + (q4 << 1);
            float b0 = bias[col];
            float b1 = bias[col + 1];
            float2 v0 = make_float2(acc[mt][nt][0] + b0, acc[mt][nt][1] + b1);
            float2 v1 = make_float2(acc[mt][nt][2] + b0, acc[mt][nt][3] + b1);
            if (MODE == 1) {
                int which = col / HID;
                int hn    = col % HID;
                int head  = hn / DHEAD;
                int dc    = hn % DHEAD;
                float *dst = (which == 0) ? g_q : ((which == 1) ? g_k : g_v);
                int bi = row / SEQ;
                int si = row % SEQ;
                size_t base = ((size_t)(bi * NHEAD + head) * SEQ + si) * DHEAD + dc;
                *(float2 *)(dst + base) = v0;
                *(float2 *)(dst + base + (size_t)8 * DHEAD) = v1;
            } else {
                *(float2 *)(Cout + (size_t)row * N + col) = v0;
                *(float2 *)(Cout + (size_t)(row + 8) * N + col) = v1;
            }
        }
    }
}

// ---------------------------------------------------------------------------
// Flash attention (causal), bf16x3 on tensor pipe.
// CTA: 128 Q rows, 8 warps (16 rows each). KV tile 64. d = 128.
// Pre-split packed operands in smem; KV double-buffered; P stays in registers.
// smem u32: Qhi[128*68] Qlo | per stage: Khi[64*68] Klo Vhi[128*36] Vlo
// ---------------------------------------------------------------------------
#define FL_Q    (128 * 68)
#define FL_K    (64 * 68)
#define FL_V    (128 * 36)
#define FL_STG  (2 * FL_K + 2 * FL_V)
#define FLASH_SMEM ((2 * FL_Q + 2 * FL_STG) * 4)

__global__ void __launch_bounds__(256) flash_causal() {
    extern __shared__ uint32_t smf[];
    uint32_t *Qhi = smf;
    uint32_t *Qlo = Qhi + FL_Q;

    const int qt   = blockIdx.x;
    const int h    = blockIdx.y;
    const int b    = blockIdx.z;
    const int tid  = threadIdx.x;
    const int lane = tid & 31;
    const int warp = tid >> 5;
    const int g    = lane >> 2;
    const int q4   = lane & 3;

    const size_t headoff = (size_t)(b * NHEAD + h) * SEQ * DHEAD;
    const float *Qg = g_q + headoff;
    const float *Kg = g_k + headoff;
    const float *Vg = g_v + headoff;

    const int   qr0   = qt * 128;
    const float scale = 0.088388347648318447f;  // 128^-0.5

    // Load + split Q tile (scaled)
    for (int i = tid; i < 128 * 32; i += 256) {
        int row = i >> 5;
        int c4  = i & 31;
        float4 fv = *(const float4 *)(Qg + (size_t)(qr0 + row) * DHEAD + 4 * c4);
        fv.x *= scale; fv.y *= scale; fv.z *= scale; fv.w *= scale;
        uint32_t h0, l0, h1, l1;
        split_pack(fv.x, fv.y, h0, l0);
        split_pack(fv.z, fv.w, h1, l1);
        int o = row * 68 + 2 * c4;
        Qhi[o] = h0; Qhi[o + 1] = h1;
        Qlo[o] = l0; Qlo[o + 1] = l1;
    }

    auto copy_kv = [&](int kv0, int st) {
        uint32_t *Kh = smf + 2 * FL_Q + st * FL_STG;
        uint32_t *Kl = Kh + FL_K;
        uint32_t *Vh = Kl + FL_K;
        uint32_t *Vl = Vh + FL_V;
        // K: [s][d] rows, packed along d
        for (int i = tid; i < 64 * 32; i += 256) {
            int row = i >> 5;
            int c4  = i & 31;
            float4 fv = *(const float4 *)(Kg + (size_t)(kv0 + row) * DHEAD + 4 * c4);
            uint32_t h0, l0, h1, l1;
            split_pack(fv.x, fv.y, h0, l0);
            split_pack(fv.z, fv.w, h1, l1);
            int o = row * 68 + 2 * c4;
            Kh[o] = h0; Kh[o + 1] = h1;
            Kl[o] = l0; Kl[o + 1] = l1;
        }
        // V: transpose-pack along s: Vh[d][s/2]
        for (int i = tid; i < 32 * 32; i += 256) {
            int rp = i >> 5;
            int c4 = i & 31;
            const float *vp = Vg + (size_t)(kv0 + 2 * rp) * DHEAD + 4 * c4;
            float4 va = *(const float4 *)vp;
            float4 vb = *(const float4 *)(vp + DHEAD);
            const float *pa = (const float *)&va;
            const float *pb = (const float *)&vb;
#pragma unroll
            for (int j = 0; j < 4; j++) {
                uint32_t hh, ll;
                split_pack(pa[j], pb[j], hh, ll);
                Vh[(4 * c4 + j) * 36 + rp] = hh;
                Vl[(4 * c4 + j) * 36 + rp] = ll;
            }
        }
    };

    float Oacc[16][4];
#pragma unroll
    for (int i = 0; i < 16; i++)
#pragma unroll
        for (int e = 0; e < 4; e++) Oacc[i][e] = 0.f;
    float m_i[2] = {-1e30f, -1e30f};
    float l_i[2] = {0.f, 0.f};

    const int wr0   = warp * 16;
    const int grow0 = qr0 + wr0;
    const int jmax  = 2 * qt + 1;

    copy_kv(0, 0);
    __syncthreads();

    for (int j = 0; j <= jmax; j++) {
        const int kv0 = j * 64;
        if (j + 1 <= jmax) copy_kv((j + 1) * 64, (j + 1) & 1);

        if (kv0 <= grow0 + 15) {
            const uint32_t *Kh = smf + 2 * FL_Q + (j & 1) * FL_STG;
            const uint32_t *Kl = Kh + FL_K;
            const uint32_t *Vh = Kl + FL_K;
            const uint32_t *Vl = Vh + FL_V;

            // ---- S = Q @ K^T : 16 x 64 per warp ----
            float sacc[8][4];
#pragma unroll
            for (int nt = 0; nt < 8; nt++)
#pragma unroll
                for (int e = 0; e < 4; e++) sacc[nt][e] = 0.f;

#pragma unroll
            for (int kk = 0; kk < 8; kk++) {
                const int kp0 = kk * 8 + q4;
                const int r   = wr0 + g;
                uint32_t ah[4], al[4];
                ah[0] = Qhi[r * 68 + kp0];
                ah[1] = Qhi[(r + 8) * 68 + kp0];
                ah[2] = Qhi[r * 68 + kp0 + 4];
                ah[3] = Qhi[(r + 8) * 68 + kp0 + 4];
                al[0] = Qlo[r * 68 + kp0];
                al[1] = Qlo[(r + 8) * 68 + kp0];
                al[2] = Qlo[r * 68 + kp0 + 4];
                al[3] = Qlo[(r + 8) * 68 + kp0 + 4];
#pragma unroll
                for (int nt = 0; nt < 8; nt++) {
                    int n = nt * 8 + g;
                    uint32_t bh0 = Kh[n * 68 + kp0];
                    uint32_t bh1 = Kh[n * 68 + kp0 + 4];
                    uint32_t bl0 = Kl[n * 68 + kp0];
                    uint32_t bl1 = Kl[n * 68 + kp0 + 4];
                    mma3(sacc[nt], ah, al, bh0, bh1, bl0, bl1);
                }
            }

            // ---- causal mask (near diagonal only) ----
            if (kv0 + 63 > grow0) {
                const int r0 = grow0 + g;
#pragma unroll
                for (int nt = 0; nt < 8; nt++) {
                    int c0 = kv0 + nt * 8 + (q4 << 1);
                    if (c0 > r0)         sacc[nt][0] = -1e30f;
                    if (c0 + 1 > r0)     sacc[nt][1] = -1e30f;
                    if (c0 > r0 + 8)     sacc[nt][2] = -1e30f;
                    if (c0 + 1 > r0 + 8) sacc[nt][3] = -1e30f;
                }
            }

            // ---- streaming softmax ----
            float rmax0 = -1e30f, rmax1 = -1e30f;
#pragma unroll
            for (int nt = 0; nt < 8; nt++) {
                rmax0 = fmaxf(rmax0, fmaxf(sacc[nt][0], sacc[nt][1]));
                rmax1 = fmaxf(rmax1, fmaxf(sacc[nt][2], sacc[nt][3]));
            }
            rmax0 = fmaxf(rmax0, __shfl_xor_sync(0xffffffffu, rmax0, 1));
            rmax0 = fmaxf(rmax0, __shfl_xor_sync(0xffffffffu, rmax0, 2));
            rmax1 = fmaxf(rmax1, __shfl_xor_sync(0xffffffffu, rmax1, 1));
            rmax1 = fmaxf(rmax1, __shfl_xor_sync(0xffffffffu, rmax1, 2));

            float mn0 = fmaxf(m_i[0], rmax0);
            float mn1 = fmaxf(m_i[1], rmax1);
            float alpha0 = __expf(m_i[0] - mn0);
            float alpha1 = __expf(m_i[1] - mn1);

            float rs0 = 0.f, rs1 = 0.f;
#pragma unroll
            for (int nt = 0; nt < 8; nt++) {
                sacc[nt][0] = __expf(sacc[nt][0] - mn0);
                sacc[nt][1] = __expf(sacc[nt][1] - mn0);
                sacc[nt][2] = __expf(sacc[nt][2] - mn1);
                sacc[nt][3] = __expf(sacc[nt][3] - mn1);
                rs0 += sacc[nt][0] + sacc[nt][1];
                rs1 += sacc[nt][2] + sacc[nt][3];
            }
            rs0 += __shfl_xor_sync(0xffffffffu, rs0, 1);
            rs0 += __shfl_xor_sync(0xffffffffu, rs0, 2);
            rs1 += __shfl_xor_sync(0xffffffffu, rs1, 1);
            rs1 += __shfl_xor_sync(0xffffffffu, rs1, 2);

            l_i[0] = l_i[0] * alpha0 + rs0;
            l_i[1] = l_i[1] * alpha1 + rs1;
            m_i[0] = mn0;
            m_i[1] = mn1;

#pragma unroll
            for (int nt = 0; nt < 16; nt++) {
                Oacc[nt][0] *= alpha0; Oacc[nt][1] *= alpha0;
                Oacc[nt][2] *= alpha1; Oacc[nt][3] *= alpha1;
            }

            // ---- O += P @ V, P repacked in registers ----
#pragma unroll
            for (int c = 0; c < 4; c++) {
                uint32_t ph[4], pl[4];
                split_pack(sacc[2 * c][0],     sacc[2 * c][1],     ph[0], pl[0]);
                split_pack(sacc[2 * c][2],     sacc[2 * c][3],     ph[1], pl[1]);
                split_pack(sacc[2 * c + 1][0], sacc[2 * c + 1][1], ph[2], pl[2]);
                split_pack(sacc[2 * c + 1][2], sacc[2 * c + 1][3], ph[3], pl[3]);
                const int kp0 = c * 8 + q4;
#pragma unroll
                for (int nt = 0; nt < 16; nt++) {
                    int n = nt * 8 + g;
                    uint32_t bh0 = Vh[n * 36 + kp0];
                    uint32_t bh1 = Vh[n * 36 + kp0 + 4];
                    uint32_t bl0 = Vl[n * 36 + kp0];
                    uint32_t bl1 = Vl[n * 36 + kp0 + 4];
                    mma3(Oacc[nt], ph, pl, bh0, bh1, bl0, bl1);
                }
            }
        }
        __syncthreads();
    }

    // ---- epilogue ----
    const float inv0 = 1.f / l_i[0];
    const float inv1 = 1.f / l_i[1];
    const int   s0   = qr0 + wr0 + g;
    const size_t rowbase0 = ((size_t)(b * SEQ) + s0) * HID + h * DHEAD;
    const size_t rowbase1 = rowbase0 + (size_t)8 * HID;
#pragma unroll
    for (int nt = 0; nt < 16; nt++) {
        int col = nt * 8 + (q4 << 1);
        float2 v0 = make_float2(Oacc[nt][0] * inv0, Oacc[nt][1] * inv0);
        float2 v1 = make_float2(Oacc[nt][2] * inv1, Oacc[nt][3] * inv1);
        *(float2 *)(g_attn + rowbase0 + col) = v0;
        *(float2 *)(g_attn + rowbase1 + col) = v1;
    }
}

// ---------------------------------------------------------------------------
// kernel_launch
// Inputs: hidden_states, w_attn, b_attn, w_proj, b_proj
// ---------------------------------------------------------------------------
extern "C" void kernel_launch(void *const *d_in, const int *in_sizes, int n_in,
                              void *d_out, int out_size) {
    (void)in_sizes; (void)n_in; (void)out_size;
    const float *hs     = (const float *)d_in[0];
    const float *w_attn = (const float *)d_in[1];
    const float *b_attn = (const float *)d_in[2];
    const float *w_proj = (const float *)d_in[3];
    const float *b_proj = (const float *)d_in[4];
    float *out = (float *)d_out;

    cudaFuncSetAttribute(gemm_bf16x3<1>,
                         cudaFuncAttributeMaxDynamicSharedMemorySize, GEMM_SMEM);
    cudaFuncSetAttribute(gemm_bf16x3<2>,
                         cudaFuncAttributeMaxDynamicSharedMemorySize, GEMM_SMEM);
    cudaFuncSetAttribute(flash_causal,
                         cudaFuncAttributeMaxDynamicSharedMemorySize, FLASH_SMEM);

    // 1) QKV projection -> g_q/g_k/g_v
    gemm_bf16x3<1><<<dim3(NQKV / 128, MTOT / 128), 256, GEMM_SMEM>>>(
        hs, w_attn, b_attn, nullptr, MTOT, NQKV, HID);

    // 2) causal flash attention -> g_attn
    flash_causal<<<dim3(SEQ / 128, NHEAD, BB), 256, FLASH_SMEM>>>();

    // 3) output projection -> d_out
    gemm_bf16x3<2><<<dim3(HID / 128, MTOT / 128), 256, GEMM_SMEM>>>(
        nullptr, w_proj, b_proj, out, MTOT, HID, HID);
}

// round 4
// speedup vs baseline: 1.9543x; 1.4586x over previous
#include <cuda_runtime.h>
#include <cstdint>

// Problem constants (fixed by the reference)
#define BB    2
#define SEQ   2048
#define HID   2048
#define NHEAD 16
#define DHEAD 128
#define MTOT  (BB * SEQ)      // 4096
#define NQKV  (3 * HID)       // 6144

// ---------------------------------------------------------------------------
// Device scratch
// ---------------------------------------------------------------------------
__device__ float g_q[(size_t)BB * NHEAD * SEQ * DHEAD];     // [b,h,s,d] fp32
__device__ float g_k[(size_t)BB * NHEAD * SEQ * DHEAD];
__device__ float g_v[(size_t)BB * NHEAD * SEQ * DHEAD];
__device__ float g_attn[(size_t)MTOT * HID];                // [b*s, h*d] fp32

// Pre-split bf16 hi/lo operand arrays (row-major, same shapes as sources)
__device__ uint16_t g_hidh[(size_t)MTOT * HID];
__device__ uint16_t g_hidl[(size_t)MTOT * HID];
__device__ uint16_t g_wah[(size_t)HID * NQKV];
__device__ uint16_t g_wal[(size_t)HID * NQKV];
__device__ uint16_t g_wph[(size_t)HID * HID];
__device__ uint16_t g_wpl[(size_t)HID * HID];
__device__ uint16_t g_ath[(size_t)MTOT * HID];
__device__ uint16_t g_atl[(size_t)MTOT * HID];

// ---------------------------------------------------------------------------
// Helpers
// ---------------------------------------------------------------------------
__device__ __forceinline__ void split_pack(float x0, float x1,
                                           uint32_t &h, uint32_t &l) {
    asm("cvt.rn.bf16x2.f32 %0, %1, %2;" : "=r"(h) : "f"(x1), "f"(x0));
    float h0 = __uint_as_float(h << 16);
    float h1 = __uint_as_float(h & 0xffff0000u);
    asm("cvt.rn.bf16x2.f32 %0, %1, %2;" : "=r"(l) : "f"(x1 - h1), "f"(x0 - h0));
}

__device__ __forceinline__ uint32_t smem_u32(const void *p) {
    uint32_t a;
    asm("{ .reg .u64 t; cvta.to.shared.u64 t, %1; cvt.u32.u64 %0, t; }"
        : "=r"(a) : "l"(p));
    return a;
}

__device__ __forceinline__ void mma16(float *d,
                                      uint32_t a0, uint32_t a1, uint32_t a2, uint32_t a3,
                                      uint32_t b0, uint32_t b1) {
    asm volatile(
        "mma.sync.aligned.m16n8k16.row.col.f32.bf16.bf16.f32 "
        "{%0,%1,%2,%3}, {%4,%5,%6,%7}, {%8,%9}, {%0,%1,%2,%3};\n"
        : "+f"(d[0]), "+f"(d[1]), "+f"(d[2]), "+f"(d[3])
        : "r"(a0), "r"(a1), "r"(a2), "r"(a3), "r"(b0), "r"(b1));
}
__device__ __forceinline__ void mma3(float *d, const uint32_t *ah, const uint32_t *al,
                                     uint32_t bh0, uint32_t bh1,
                                     uint32_t bl0, uint32_t bl1) {
    mma16(d, ah[0], ah[1], ah[2], ah[3], bh0, bh1);
    mma16(d, ah[0], ah[1], ah[2], ah[3], bl0, bl1);
    mma16(d, al[0], al[1], al[2], al[3], bh0, bh1);
}

#define LDSM4(r, addr)                                                       \
    asm volatile("ldmatrix.sync.aligned.m8n8.x4.shared.b16 {%0,%1,%2,%3}, [%4];" \
        : "=r"((r)[0]), "=r"((r)[1]), "=r"((r)[2]), "=r"((r)[3]) : "r"(addr))
#define LDSM4T(r, addr)                                                      \
    asm volatile("ldmatrix.sync.aligned.m8n8.x4.trans.shared.b16 {%0,%1,%2,%3}, [%4];" \
        : "=r"((r)[0]), "=r"((r)[1]), "=r"((r)[2]), "=r"((r)[3]) : "r"(addr))

__device__ __forceinline__ void cpa16(uint32_t dst, const void *src) {
    asm volatile("cp.async.cg.shared.global [%0], [%1], 16;"
                 :: "r"(dst), "l"(src) : "memory");
}
#define CP_COMMIT() asm volatile("cp.async.commit_group;" ::: "memory")
#define CP_WAIT2()  asm volatile("cp.async.wait_group 2;" ::: "memory")

// ---------------------------------------------------------------------------
// Split kernel: fp32 -> bf16 hi + bf16 lo (row-major preserved)
// ---------------------------------------------------------------------------
__global__ void __launch_bounds__(256)
split4(const float4 *__restrict__ x, uint2 *__restrict__ hi, uint2 *__restrict__ lo) {
    int i = blockIdx.x * 256 + threadIdx.x;
    float4 v = x[i];
    uint32_t h0, l0, h1, l1;
    split_pack(v.x, v.y, h0, l0);
    split_pack(v.z, v.w, h1, l1);
    hi[i] = make_uint2(h0, h1);
    lo[i] = make_uint2(l0, l1);
}

// ---------------------------------------------------------------------------
// GEMM: C[M,N] = A[M,K] @ B[K,N] + bias, bf16x3.
// Inputs pre-split (Ah/Al row-major [M][K], Bh/Bl row-major [K][N]).
// CTA tile 128m x 256n, 8 warps (2 wm x 4 wn), warp tile 64x64.
// K slab 32, 3-stage cp.async pipeline, ldmatrix fragment loads.
// Stage layout (bytes): AH 128*80 | AL 128*80 | BH 32*512 | BL 32*512 = 53248.
// A rows: stride 5 chunks (16B) -> conflict-free non-trans ldmatrix.
// B rows: 32 chunks, XOR swizzle c^(k&7) -> conflict-free trans ldmatrix.
// MODE 1: QKV scatter into g_q/g_k/g_v | MODE 0: plain output.
// ---------------------------------------------------------------------------
#define STG_BYTES 53248
#define OFF_AH 0
#define OFF_AL 10240
#define OFF_BH 20480
#define OFF_BL 36864
#define GEMM_SMEM (3 * STG_BYTES)

template <int MODE>
__global__ void __launch_bounds__(256)
gemm_ldsm(const uint16_t *__restrict__ Ah, const uint16_t *__restrict__ Al,
          const uint16_t *__restrict__ Bh, const uint16_t *__restrict__ Bl,
          const float *__restrict__ bias, float *__restrict__ Cout,
          int M, int N, int K) {
    extern __shared__ char smc[];
    const uint32_t sbase = smem_u32(smc);

    const int tid  = threadIdx.x;
    const int lane = tid & 31;
    const int warp = tid >> 5;
    const int wm   = warp >> 2;      // 0..1
    const int wn   = warp & 3;       // 0..3
    const int m0   = blockIdx.y * 128;
    const int n0   = blockIdx.x * 256;
    const int g    = lane >> 2;
    const int q4   = lane & 3;

    float acc[4][8][4];
#pragma unroll
    for (int i = 0; i < 4; i++)
#pragma unroll
        for (int j = 0; j < 8; j++)
#pragma unroll
            for (int e = 0; e < 4; e++) acc[i][j][e] = 0.f;

    auto issue = [&](int s) {
        const uint32_t sb = sbase + (s % 3) * STG_BYTES;
        const int kb = s << 5;
        // A: 512 chunks each for hi/lo (128 rows x 4 chunks)
#pragma unroll
        for (int i = 0; i < 2; i++) {
            int id  = tid + i * 256;
            int row = id >> 2;
            int c   = id & 3;
            size_t gidx = (size_t)(m0 + row) * K + kb + c * 8;
            uint32_t d = (row * 5 + c) << 4;
            cpa16(sb + OFF_AH + d, Ah + gidx);
            cpa16(sb + OFF_AL + d, Al + gidx);
        }
        // B: 1024 chunks each for hi/lo (32 k-rows x 32 chunks)
#pragma unroll
        for (int i = 0; i < 4; i++) {
            int id = tid + i * 256;
            int k  = id >> 5;
            int c  = id & 31;
            size_t gidx = (size_t)(kb + k) * N + n0 + c * 8;
            uint32_t d = ((k << 5) + (c ^ (k & 7))) << 4;
            cpa16(sb + OFF_BH + d, Bh + gidx);
            cpa16(sb + OFF_BL + d, Bl + gidx);
        }
    };

    auto compute = [&](int s) {
        const uint32_t sb = sbase + (s % 3) * STG_BYTES;
#pragma unroll
        for (int kk = 0; kk < 2; kk++) {
            uint32_t ah[4][4], al[4][4];
            const int arow = wm * 64 + (lane & 15);
            const int ac   = kk * 2 + (lane >> 4);
#pragma unroll
            for (int mt = 0; mt < 4; mt++) {
                uint32_t ad = sb + OFF_AH + (((arow + mt * 16) * 5 + ac) << 4);
                LDSM4(ah[mt], ad);
                LDSM4(al[mt], ad + (OFF_AL - OFF_AH));
            }
            const int kloc = kk * 16 + ((lane >> 4) << 3) + (lane & 7);
            const int cbas = wn * 8 + ((lane >> 3) & 1);
#pragma unroll
            for (int bt = 0; bt < 4; bt++) {
                int c = cbas + bt * 2;
                uint32_t bd = sb + OFF_BH + (((kloc << 5) + (c ^ (kloc & 7))) << 4);
                uint32_t bh[4], bl[4];
                LDSM4T(bh, bd);
                LDSM4T(bl, bd + (OFF_BL - OFF_BH));
#pragma unroll
                for (int mt = 0; mt < 4; mt++) {
                    mma3(acc[mt][2 * bt],     ah[mt], al[mt], bh[0], bh[2], bl[0], bl[2]);
                    mma3(acc[mt][2 * bt + 1], ah[mt], al[mt], bh[1], bh[3], bl[1], bl[3]);
                }
            }
        }
    };

    const int S = K >> 5;
    issue(0); CP_COMMIT();
    issue(1); CP_COMMIT();
    issue(2); CP_COMMIT();

    for (int s = 0; s < S; s++) {
        CP_WAIT2();
        __syncthreads();
        compute(s);
        __syncthreads();
        if (s + 3 < S) issue(s + 3);
        CP_COMMIT();
    }

    // ---- epilogue ----
#pragma unroll
    for (int mt = 0; mt < 4; mt++) {
#pragma unroll
        for (int nt = 0; nt < 8; nt++) {
            int row = m0 + wm * 64 + mt * 16 + g;
            int col = n0 + wn * 64 + nt * 8 + (q4 << 1);
            float b0 = bias[col];
            float b1 = bias[col + 1];
            float2 v0 = make_float2(acc[mt][nt][0] + b0, acc[mt][nt][1] + b1);
            float2 v1 = make_float2(acc[mt][nt][2] + b0, acc[mt][nt][3] + b1);
            if (MODE == 1) {
                int which = col >> 11;
                int head  = (col >> 7) & 15;
                int dc    = col & 127;
                float *dst = (which == 0) ? g_q : ((which == 1) ? g_k : g_v);
                int bi = row >> 11;
                int si = row & 2047;
                size_t base = ((size_t)(bi * NHEAD + head) * SEQ + si) * DHEAD + dc;
                *(float2 *)(dst + base) = v0;
                *(float2 *)(dst + base + (size_t)8 * DHEAD) = v1;
            } else {
                *(float2 *)(Cout + (size_t)row * N + col) = v0;
                *(float2 *)(Cout + (size_t)(row + 8) * N + col) = v1;
            }
        }
    }
}

// ---------------------------------------------------------------------------
// Flash attention (causal), bf16x3 — unchanged from round 2 (passing)
// ---------------------------------------------------------------------------
#define FL_Q    (128 * 68)
#define FL_K    (64 * 68)
#define FL_V    (128 * 36)
#define FL_STG  (2 * FL_K + 2 * FL_V)
#define FLASH_SMEM ((2 * FL_Q + 2 * FL_STG) * 4)

__global__ void __launch_bounds__(256) flash_causal() {
    extern __shared__ uint32_t smf[];
    uint32_t *Qhi = smf;
    uint32_t *Qlo = Qhi + FL_Q;

    const int qt   = blockIdx.x;
    const int h    = blockIdx.y;
    const int b    = blockIdx.z;
    const int tid  = threadIdx.x;
    const int lane = tid & 31;
    const int warp = tid >> 5;
    const int g    = lane >> 2;
    const int q4   = lane & 3;

    const size_t headoff = (size_t)(b * NHEAD + h) * SEQ * DHEAD;
    const float *Qg = g_q + headoff;
    const float *Kg = g_k + headoff;
    const float *Vg = g_v + headoff;

    const int   qr0   = qt * 128;
    const float scale = 0.088388347648318447f;  // 128^-0.5

    for (int i = tid; i < 128 * 32; i += 256) {
        int row = i >> 5;
        int c4  = i & 31;
        float4 fv = *(const float4 *)(Qg + (size_t)(qr0 + row) * DHEAD + 4 * c4);
        fv.x *= scale; fv.y *= scale; fv.z *= scale; fv.w *= scale;
        uint32_t h0, l0, h1, l1;
        split_pack(fv.x, fv.y, h0, l0);
        split_pack(fv.z, fv.w, h1, l1);
        int o = row * 68 + 2 * c4;
        Qhi[o] = h0; Qhi[o + 1] = h1;
        Qlo[o] = l0; Qlo[o + 1] = l1;
    }

    auto copy_kv = [&](int kv0, int st) {
        uint32_t *Kh = smf + 2 * FL_Q + st * FL_STG;
        uint32_t *Kl = Kh + FL_K;
        uint32_t *Vh = Kl + FL_K;
        uint32_t *Vl = Vh + FL_V;
        for (int i = tid; i < 64 * 32; i += 256) {
            int row = i >> 5;
            int c4  = i & 31;
            float4 fv = *(const float4 *)(Kg + (size_t)(kv0 + row) * DHEAD + 4 * c4);
            uint32_t h0, l0, h1, l1;
            split_pack(fv.x, fv.y, h0, l0);
            split_pack(fv.z, fv.w, h1, l1);
            int o = row * 68 + 2 * c4;
            Kh[o] = h0; Kh[o + 1] = h1;
            Kl[o] = l0; Kl[o + 1] = l1;
        }
        for (int i = tid; i < 32 * 32; i += 256) {
            int rp = i >> 5;
            int c4 = i & 31;
            const float *vp = Vg + (size_t)(kv0 + 2 * rp) * DHEAD + 4 * c4;
            float4 va = *(const float4 *)vp;
            float4 vb = *(const float4 *)(vp + DHEAD);
            const float *pa = (const float *)&va;
            const float *pb = (const float *)&vb;
#pragma unroll
            for (int j = 0; j < 4; j++) {
                uint32_t hh, ll;
                split_pack(pa[j], pb[j], hh, ll);
                Vh[(4 * c4 + j) * 36 + rp] = hh;
                Vl[(4 * c4 + j) * 36 + rp] = ll;
            }
        }
    };

    float Oacc[16][4];
#pragma unroll
    for (int i = 0; i < 16; i++)
#pragma unroll
        for (int e = 0; e < 4; e++) Oacc[i][e] = 0.f;
    float m_i[2] = {-1e30f, -1e30f};
    float l_i[2] = {0.f, 0.f};

    const int wr0   = warp * 16;
    const int grow0 = qr0 + wr0;
    const int jmax  = 2 * qt + 1;

    copy_kv(0, 0);
    __syncthreads();

    for (int j = 0; j <= jmax; j++) {
        const int kv0 = j * 64;
        if (j + 1 <= jmax) copy_kv((j + 1) * 64, (j + 1) & 1);

        if (kv0 <= grow0 + 15) {
            const uint32_t *Kh = smf + 2 * FL_Q + (j & 1) * FL_STG;
            const uint32_t *Kl = Kh + FL_K;
            const uint32_t *Vh = Kl + FL_K;
            const uint32_t *Vl = Vh + FL_V;

            float sacc[8][4];
#pragma unroll
            for (int nt = 0; nt < 8; nt++)
#pragma unroll
                for (int e = 0; e < 4; e++) sacc[nt][e] = 0.f;

#pragma unroll
            for (int kk = 0; kk < 8; kk++) {
                const int kp0 = kk * 8 + q4;
                const int r   = wr0 + g;
                uint32_t ah[4], al[4];
                ah[0] = Qhi[r * 68 + kp0];
                ah[1] = Qhi[(r + 8) * 68 + kp0];
                ah[2] = Qhi[r * 68 + kp0 + 4];
                ah[3] = Qhi[(r + 8) * 68 + kp0 + 4];
                al[0] = Qlo[r * 68 + kp0];
                al[1] = Qlo[(r + 8) * 68 + kp0];
                al[2] = Qlo[r * 68 + kp0 + 4];
                al[3] = Qlo[(r + 8) * 68 + kp0 + 4];
#pragma unroll
                for (int nt = 0; nt < 8; nt++) {
                    int n = nt * 8 + g;
                    uint32_t bh0 = Kh[n * 68 + kp0];
                    uint32_t bh1 = Kh[n * 68 + kp0 + 4];
                    uint32_t bl0 = Kl[n * 68 + kp0];
                    uint32_t bl1 = Kl[n * 68 + kp0 + 4];
                    mma3(sacc[nt], ah, al, bh0, bh1, bl0, bl1);
                }
            }

            if (kv0 + 63 > grow0) {
                const int r0 = grow0 + g;
#pragma unroll
                for (int nt = 0; nt < 8; nt++) {
                    int c0 = kv0 + nt * 8 + (q4 << 1);
                    if (c0 > r0)         sacc[nt][0] = -1e30f;
                    if (c0 + 1 > r0)     sacc[nt][1] = -1e30f;
                    if (c0 > r0 + 8)     sacc[nt][2] = -1e30f;
                    if (c0 + 1 > r0 + 8) sacc[nt][3] = -1e30f;
                }
            }

            float rmax0 = -1e30f, rmax1 = -1e30f;
#pragma unroll
            for (int nt = 0; nt < 8; nt++) {
                rmax0 = fmaxf(rmax0, fmaxf(sacc[nt][0], sacc[nt][1]));
                rmax1 = fmaxf(rmax1, fmaxf(sacc[nt][2], sacc[nt][3]));
            }
            rmax0 = fmaxf(rmax0, __shfl_xor_sync(0xffffffffu, rmax0, 1));
            rmax0 = fmaxf(rmax0, __shfl_xor_sync(0xffffffffu, rmax0, 2));
            rmax1 = fmaxf(rmax1, __shfl_xor_sync(0xffffffffu, rmax1, 1));
            rmax1 = fmaxf(rmax1, __shfl_xor_sync(0xffffffffu, rmax1, 2));

            float mn0 = fmaxf(m_i[0], rmax0);
            float mn1 = fmaxf(m_i[1], rmax1);
            float alpha0 = __expf(m_i[0] - mn0);
            float alpha1 = __expf(m_i[1] - mn1);

            float rs0 = 0.f, rs1 = 0.f;
#pragma unroll
            for (int nt = 0; nt < 8; nt++) {
                sacc[nt][0] = __expf(sacc[nt][0] - mn0);
                sacc[nt][1] = __expf(sacc[nt][1] - mn0);
                sacc[nt][2] = __expf(sacc[nt][2] - mn1);
                sacc[nt][3] = __expf(sacc[nt][3] - mn1);
                rs0 += sacc[nt][0] + sacc[nt][1];
                rs1 += sacc[nt][2] + sacc[nt][3];
            }
            rs0 += __shfl_xor_sync(0xffffffffu, rs0, 1);
            rs0 += __shfl_xor_sync(0xffffffffu, rs0, 2);
            rs1 += __shfl_xor_sync(0xffffffffu, rs1, 1);
            rs1 += __shfl_xor_sync(0xffffffffu, rs1, 2);

            l_i[0] = l_i[0] * alpha0 + rs0;
            l_i[1] = l_i[1] * alpha1 + rs1;
            m_i[0] = mn0;
            m_i[1] = mn1;

#pragma unroll
            for (int nt = 0; nt < 16; nt++) {
                Oacc[nt][0] *= alpha0; Oacc[nt][1] *= alpha0;
                Oacc[nt][2] *= alpha1; Oacc[nt][3] *= alpha1;
            }

#pragma unroll
            for (int c = 0; c < 4; c++) {
                uint32_t ph[4], pl[4];
                split_pack(sacc[2 * c][0],     sacc[2 * c][1],     ph[0], pl[0]);
                split_pack(sacc[2 * c][2],     sacc[2 * c][3],     ph[1], pl[1]);
                split_pack(sacc[2 * c + 1][0], sacc[2 * c + 1][1], ph[2], pl[2]);
                split_pack(sacc[2 * c + 1][2], sacc[2 * c + 1][3], ph[3], pl[3]);
                const int kp0 = c * 8 + q4;
#pragma unroll
                for (int nt = 0; nt < 16; nt++) {
                    int n = nt * 8 + g;
                    uint32_t bh0 = Vh[n * 36 + kp0];
                    uint32_t bh1 = Vh[n * 36 + kp0 + 4];
                    uint32_t bl0 = Vl[n * 36 + kp0];
                    uint32_t bl1 = Vl[n * 36 + kp0 + 4];
                    mma3(Oacc[nt], ph, pl, bh0, bh1, bl0, bl1);
                }
            }
        }
        __syncthreads();
    }

    const float inv0 = 1.f / l_i[0];
    const float inv1 = 1.f / l_i[1];
    const int   s0   = qr0 + wr0 + g;
    const size_t rowbase0 = ((size_t)(b * SEQ) + s0) * HID + h * DHEAD;
    const size_t rowbase1 = rowbase0 + (size_t)8 * HID;
#pragma unroll
    for (int nt = 0; nt < 16; nt++) {
        int col = nt * 8 + (q4 << 1);
        float2 v0 = make_float2(Oacc[nt][0] * inv0, Oacc[nt][1] * inv0);
        float2 v1 = make_float2(Oacc[nt][2] * inv1, Oacc[nt][3] * inv1);
        *(float2 *)(g_attn + rowbase0 + col) = v0;
        *(float2 *)(g_attn + rowbase1 + col) = v1;
    }
}

// ---------------------------------------------------------------------------
// kernel_launch
// ---------------------------------------------------------------------------
extern "C" void kernel_launch(void *const *d_in, const int *in_sizes, int n_in,
                              void *d_out, int out_size) {
    (void)in_sizes; (void)n_in; (void)out_size;
    const float *hs     = (const float *)d_in[0];
    const float *w_attn = (const float *)d_in[1];
    const float *b_attn = (const float *)d_in[2];
    const float *w_proj = (const float *)d_in[3];
    const float *b_proj = (const float *)d_in[4];
    float *out = (float *)d_out;

    cudaFuncSetAttribute(gemm_ldsm<1>,
                         cudaFuncAttributeMaxDynamicSharedMemorySize, GEMM_SMEM);
    cudaFuncSetAttribute(gemm_ldsm<0>,
                         cudaFuncAttributeMaxDynamicSharedMemorySize, GEMM_SMEM);
    cudaFuncSetAttribute(flash_causal,
                         cudaFuncAttributeMaxDynamicSharedMemorySize, FLASH_SMEM);

    uint16_t *hidh, *hidl, *wah, *wal, *wph, *wpl, *ath, *atl;
    cudaGetSymbolAddress((void **)&hidh, g_hidh);
    cudaGetSymbolAddress((void **)&hidl, g_hidl);
    cudaGetSymbolAddress((void **)&wah,  g_wah);
    cudaGetSymbolAddress((void **)&wal,  g_wal);
    cudaGetSymbolAddress((void **)&wph,  g_wph);
    cudaGetSymbolAddress((void **)&wpl,  g_wpl);
    cudaGetSymbolAddress((void **)&ath,  g_ath);
    cudaGetSymbolAddress((void **)&atl,  g_atl);
    float *attnf;
    cudaGetSymbolAddress((void **)&attnf, g_attn);

    // 0) pre-split inputs to bf16 hi/lo
    split4<<<(MTOT * HID) / 1024, 256>>>((const float4 *)hs,
                                         (uint2 *)hidh, (uint2 *)hidl);
    split4<<<(HID * NQKV) / 1024, 256>>>((const float4 *)w_attn,
                                         (uint2 *)wah, (uint2 *)wal);
    split4<<<(HID * HID) / 1024, 256>>>((const float4 *)w_proj,
                                        (uint2 *)wph, (uint2 *)wpl);

    // 1) QKV projection -> g_q/g_k/g_v
    gemm_ldsm<1><<<dim3(NQKV / 256, MTOT / 128), 256, GEMM_SMEM>>>(
        hidh, hidl, wah, wal, b_attn, nullptr, MTOT, NQKV, HID);

    // 2) causal flash attention -> g_attn
    flash_causal<<<dim3(SEQ / 128, NHEAD, BB), 256, FLASH_SMEM>>>();

    // 2b) split attention output for proj GEMM
    split4<<<(MTOT * HID) / 1024, 256>>>((const float4 *)attnf,
                                         (uint2 *)ath, (uint2 *)atl);

    // 3) output projection -> d_out
    gemm_ldsm<0><<<dim3(HID / 256, MTOT / 128), 256, GEMM_SMEM>>>(
        ath, atl, wph, wpl, b_proj, out, MTOT, HID, HID);
}

// round 6
// speedup vs baseline: 2.2842x; 1.1688x over previous
#include <cuda_runtime.h>
#include <cstdint>

// Problem constants (fixed by the reference)
#define BB    2
#define SEQ   2048
#define HID   2048
#define NHEAD 16
#define DHEAD 128
#define MTOT  (BB * SEQ)      // 4096
#define NQKV  (3 * HID)       // 6144
#define QSCALE 0.088388347648318447f

// ---------------------------------------------------------------------------
// Device scratch (all 16B-aligned for cp.async / vector access)
// ---------------------------------------------------------------------------
__device__ __align__(128) uint16_t g_qh[(size_t)BB * NHEAD * SEQ * DHEAD];
__device__ __align__(128) uint16_t g_ql[(size_t)BB * NHEAD * SEQ * DHEAD];
__device__ __align__(128) uint16_t g_kh[(size_t)BB * NHEAD * SEQ * DHEAD];
__device__ __align__(128) uint16_t g_kl[(size_t)BB * NHEAD * SEQ * DHEAD];
__device__ __align__(128) uint16_t g_vh[(size_t)BB * NHEAD * SEQ * DHEAD];
__device__ __align__(128) uint16_t g_vl[(size_t)BB * NHEAD * SEQ * DHEAD];

__device__ __align__(128) uint16_t g_hidh[(size_t)MTOT * HID];
__device__ __align__(128) uint16_t g_hidl[(size_t)MTOT * HID];
__device__ __align__(128) uint16_t g_wah[(size_t)HID * NQKV];
__device__ __align__(128) uint16_t g_wal[(size_t)HID * NQKV];
__device__ __align__(128) uint16_t g_wph[(size_t)HID * HID];
__device__ __align__(128) uint16_t g_wpl[(size_t)HID * HID];
__device__ __align__(128) uint16_t g_ath[(size_t)MTOT * HID];
__device__ __align__(128) uint16_t g_atl[(size_t)MTOT * HID];

// ---------------------------------------------------------------------------
// Helpers
// ---------------------------------------------------------------------------
__device__ __forceinline__ void split_pack(float x0, float x1,
                                           uint32_t &h, uint32_t &l) {
    asm("cvt.rn.bf16x2.f32 %0, %1, %2;" : "=r"(h) : "f"(x1), "f"(x0));
    float h0 = __uint_as_float(h << 16);
    float h1 = __uint_as_float(h & 0xffff0000u);
    asm("cvt.rn.bf16x2.f32 %0, %1, %2;" : "=r"(l) : "f"(x1 - h1), "f"(x0 - h0));
}

__device__ __forceinline__ uint32_t smem_u32(const void *p) {
    uint32_t a;
    asm("{ .reg .u64 t; cvta.to.shared.u64 t, %1; cvt.u32.u64 %0, t; }"
        : "=r"(a) : "l"(p));
    return a;
}

__device__ __forceinline__ void mma16(float *d,
                                      uint32_t a0, uint32_t a1, uint32_t a2, uint32_t a3,
                                      uint32_t b0, uint32_t b1) {
    asm volatile(
        "mma.sync.aligned.m16n8k16.row.col.f32.bf16.bf16.f32 "
        "{%0,%1,%2,%3}, {%4,%5,%6,%7}, {%8,%9}, {%0,%1,%2,%3};\n"
        : "+f"(d[0]), "+f"(d[1]), "+f"(d[2]), "+f"(d[3])
        : "r"(a0), "r"(a1), "r"(a2), "r"(a3), "r"(b0), "r"(b1));
}
__device__ __forceinline__ void mma3(float *d, const uint32_t *ah, const uint32_t *al,
                                     uint32_t bh0, uint32_t bh1,
                                     uint32_t bl0, uint32_t bl1) {
    mma16(d, ah[0], ah[1], ah[2], ah[3], bh0, bh1);
    mma16(d, ah[0], ah[1], ah[2], ah[3], bl0, bl1);
    mma16(d, al[0], al[1], al[2], al[3], bh0, bh1);
}

#define LDSM4(r, addr)                                                       \
    asm volatile("ldmatrix.sync.aligned.m8n8.x4.shared.b16 {%0,%1,%2,%3}, [%4];" \
        : "=r"((r)[0]), "=r"((r)[1]), "=r"((r)[2]), "=r"((r)[3]) : "r"(addr))
#define LDSM4T(r, addr)                                                      \
    asm volatile("ldmatrix.sync.aligned.m8n8.x4.trans.shared.b16 {%0,%1,%2,%3}, [%4];" \
        : "=r"((r)[0]), "=r"((r)[1]), "=r"((r)[2]), "=r"((r)[3]) : "r"(addr))

__device__ __forceinline__ void cpa16(uint32_t dst, const void *src) {
    asm volatile("cp.async.cg.shared.global [%0], [%1], 16;"
                 :: "r"(dst), "l"(src) : "memory");
}
#define CP_COMMIT() asm volatile("cp.async.commit_group;" ::: "memory")
#define CP_WAIT2()  asm volatile("cp.async.wait_group 2;" ::: "memory")
#define CP_WAIT0()  asm volatile("cp.async.wait_group 0;" ::: "memory")

// ---------------------------------------------------------------------------
// Split kernel: fp32 -> bf16 hi + bf16 lo (row-major preserved)
// ---------------------------------------------------------------------------
__global__ void __launch_bounds__(256)
split4(const float4 *__restrict__ x, uint2 *__restrict__ hi, uint2 *__restrict__ lo) {
    int i = blockIdx.x * 256 + threadIdx.x;
    float4 v = x[i];
    uint32_t h0, l0, h1, l1;
    split_pack(v.x, v.y, h0, l0);
    split_pack(v.z, v.w, h1, l1);
    hi[i] = make_uint2(h0, h1);
    lo[i] = make_uint2(l0, l1);
}

// ---------------------------------------------------------------------------
// GEMM: C = A @ B + bias, bf16x3, pre-split inputs, 4-stage cp.async,
// CTA 128m x 256n, warp tile 64x64, ldmatrix fragments.
// MODE 1: QKV epilogue -> split bf16 q/k/v (Q pre-scaled) | MODE 0: fp32 out.
// ---------------------------------------------------------------------------
#define STG_BYTES 53248
#define OFF_AH 0
#define OFF_AL 10240
#define OFF_BH 20480
#define OFF_BL 36864
#define GEMM_SMEM (4 * STG_BYTES)

template <int MODE>
__global__ void __launch_bounds__(256)
gemm_ldsm(const uint16_t *__restrict__ Ah, const uint16_t *__restrict__ Al,
          const uint16_t *__restrict__ Bh, const uint16_t *__restrict__ Bl,
          const float *__restrict__ bias, float *__restrict__ Cout,
          int M, int N, int K) {
    extern __shared__ char smc[];
    const uint32_t sbase = smem_u32(smc);

    const int tid  = threadIdx.x;
    const int lane = tid & 31;
    const int warp = tid >> 5;
    const int wm   = warp >> 2;
    const int wn   = warp & 3;
    const int m0   = blockIdx.y * 128;
    const int n0   = blockIdx.x * 256;
    const int g    = lane >> 2;
    const int q4   = lane & 3;

    float acc[4][8][4];
#pragma unroll
    for (int i = 0; i < 4; i++)
#pragma unroll
        for (int j = 0; j < 8; j++)
#pragma unroll
            for (int e = 0; e < 4; e++) acc[i][j][e] = 0.f;

    auto issue = [&](int s) {
        const uint32_t sb = sbase + (s & 3) * STG_BYTES;
        const int kb = s << 5;
#pragma unroll
        for (int i = 0; i < 2; i++) {
            int id  = tid + i * 256;
            int row = id >> 2;
            int c   = id & 3;
            size_t gidx = (size_t)(m0 + row) * K + kb + c * 8;
            uint32_t d = (row * 5 + c) << 4;
            cpa16(sb + OFF_AH + d, Ah + gidx);
            cpa16(sb + OFF_AL + d, Al + gidx);
        }
#pragma unroll
        for (int i = 0; i < 4; i++) {
            int id = tid + i * 256;
            int k  = id >> 5;
            int c  = id & 31;
            size_t gidx = (size_t)(kb + k) * N + n0 + c * 8;
            uint32_t d = ((k << 5) + (c ^ (k & 7))) << 4;
            cpa16(sb + OFF_BH + d, Bh + gidx);
            cpa16(sb + OFF_BL + d, Bl + gidx);
        }
    };

    auto compute = [&](int s) {
        const uint32_t sb = sbase + (s & 3) * STG_BYTES;
        const int arow = wm * 64 + (lane & 15);
        const int lt16 = lane >> 4;
        const int cbas = wn * 8 + ((lane >> 3) & 1);
#pragma unroll
        for (int kk = 0; kk < 2; kk++) {
            const int ac = kk * 2 + lt16;
            uint32_t ah[4][4], al[4][4];
#pragma unroll
            for (int mt = 0; mt < 4; mt++) {
                uint32_t ad = sb + OFF_AH + (((arow + mt * 16) * 5 + ac) << 4);
                LDSM4(ah[mt], ad);
                LDSM4(al[mt], ad + (OFF_AL - OFF_AH));
            }
            const int kloc = kk * 16 + (lt16 << 3) + (lane & 7);
            uint32_t bh[2][4], bl[2][4];
            {
                uint32_t bd = sb + OFF_BH +
                              (((kloc << 5) + (cbas ^ (kloc & 7))) << 4);
                LDSM4T(bh[0], bd);
                LDSM4T(bl[0], bd + (OFF_BL - OFF_BH));
            }
#pragma unroll
            for (int bt = 0; bt < 4; bt++) {
                if (bt < 3) {
                    int c = cbas + (bt + 1) * 2;
                    uint32_t bd = sb + OFF_BH +
                                  (((kloc << 5) + (c ^ (kloc & 7))) << 4);
                    LDSM4T(bh[(bt + 1) & 1], bd);
                    LDSM4T(bl[(bt + 1) & 1], bd + (OFF_BL - OFF_BH));
                }
                const uint32_t *BH = bh[bt & 1];
                const uint32_t *BL = bl[bt & 1];
#pragma unroll
                for (int mt = 0; mt < 4; mt++) {
                    mma3(acc[mt][2 * bt],     ah[mt], al[mt], BH[0], BH[2], BL[0], BL[2]);
                    mma3(acc[mt][2 * bt + 1], ah[mt], al[mt], BH[1], BH[3], BL[1], BL[3]);
                }
            }
        }
    };

    const int S = K >> 5;
    issue(0); CP_COMMIT();
    issue(1); CP_COMMIT();
    issue(2); CP_COMMIT();

    for (int s = 0; s < S; s++) {
        CP_WAIT2();
        __syncthreads();
        compute(s);
        if (s + 3 < S) issue(s + 3);
        CP_COMMIT();
    }

    // ---- epilogue ----
#pragma unroll
    for (int mt = 0; mt < 4; mt++) {
#pragma unroll
        for (int nt = 0; nt < 8; nt++) {
            int row = m0 + wm * 64 + mt * 16 + g;
            int col = n0 + wn * 64 + nt * 8 + (q4 << 1);
            float b0 = bias[col];
            float b1 = bias[col + 1];
            if (MODE == 1) {
                int which = col >> 11;
                int head  = (col >> 7) & 15;
                int dc    = col & 127;
                uint16_t *dh = (which == 0) ? g_qh : ((which == 1) ? g_kh : g_vh);
                uint16_t *dl = (which == 0) ? g_ql : ((which == 1) ? g_kl : g_vl);
                float sc = (which == 0) ? QSCALE : 1.f;
                float v00 = (acc[mt][nt][0] + b0) * sc;
                float v01 = (acc[mt][nt][1] + b1) * sc;
                float v10 = (acc[mt][nt][2] + b0) * sc;
                float v11 = (acc[mt][nt][3] + b1) * sc;
                uint32_t h0, l0, h1, l1;
                split_pack(v00, v01, h0, l0);
                split_pack(v10, v11, h1, l1);
                int bi = row >> 11;
                int si = row & 2047;
                size_t u32i = (((size_t)(bi * NHEAD + head) * SEQ + si) * DHEAD + dc) >> 1;
                ((uint32_t *)dh)[u32i] = h0;
                ((uint32_t *)dl)[u32i] = l0;
                ((uint32_t *)dh)[u32i + 8 * 64] = h1;
                ((uint32_t *)dl)[u32i + 8 * 64] = l1;
            } else {
                float2 v0 = make_float2(acc[mt][nt][0] + b0, acc[mt][nt][1] + b1);
                float2 v1 = make_float2(acc[mt][nt][2] + b0, acc[mt][nt][3] + b1);
                *(float2 *)(Cout + (size_t)row * N + col) = v0;
                *(float2 *)(Cout + (size_t)(row + 8) * N + col) = v1;
            }
        }
    }
}

// ---------------------------------------------------------------------------
// Flash attention (causal), bf16x3, ldmatrix fragments, pure cp.async loads.
// CTA: 128 Q rows, 8 warps x 16 rows. KV tile 64. d = 128.
// smem u32: Qh[128*68] Ql[128*68] | stage st: Kh[64*68] Kl Vh Vl (4352 each).
// Q/K frags: non-trans LDSM on [s][d] rows. V frags: trans LDSM on [s][d].
// Output: split bf16 hi/lo directly to g_ath/g_atl.
// ---------------------------------------------------------------------------
#define FL_QU   (128 * 68)          // u32 per Q array
#define FL_AU   (64 * 68)           // u32 per K/V array (4352)
#define FL_STGU (4 * FL_AU)         // 17408 u32 per stage
#define FLASH_SMEM ((2 * FL_QU + 2 * FL_STGU) * 4)

__global__ void __launch_bounds__(256) flash_causal() {
    extern __shared__ uint32_t smf[];
    const uint32_t sbase = smem_u32(smf);

    const int qt   = (gridDim.x - 1) - blockIdx.x;   // heavy tiles first
    const int h    = blockIdx.y;
    const int b    = blockIdx.z;
    const int tid  = threadIdx.x;
    const int lane = tid & 31;
    const int warp = tid >> 5;
    const int g    = lane >> 2;
    const int q4   = lane & 3;

    const size_t headoff = (size_t)(b * NHEAD + h) * SEQ * DHEAD;
    const uint16_t *Qhg = g_qh + headoff;
    const uint16_t *Qlg = g_ql + headoff;
    const uint16_t *Khg = g_kh + headoff;
    const uint16_t *Klg = g_kl + headoff;
    const uint16_t *Vhg = g_vh + headoff;
    const uint16_t *Vlg = g_vl + headoff;

    const int qr0 = qt * 128;

    // ---- Q tile: 2 arrays x (128 rows x 16 chunks) = 4096 cp.async chunks ----
#pragma unroll
    for (int i = 0; i < 16; i++) {
        int id  = tid + i * 256;       // 0..4095
        int arr = id >> 11;            // 0 = Qh, 1 = Ql
        int rc  = id & 2047;
        int row = rc >> 4;             // 0..127
        int c   = rc & 15;
        const uint16_t *src = (arr == 0 ? Qhg : Qlg) +
                              (size_t)(qr0 + row) * DHEAD + c * 8;
        cpa16(sbase + ((arr * FL_QU + row * 68 + c * 4) << 2), src);
    }

    auto copy_kv = [&](int kv0, int st) {
        const uint32_t stb = sbase + ((2 * FL_QU + st * FL_STGU) << 2);
#pragma unroll
        for (int i = 0; i < 16; i++) {
            int id  = tid + i * 256;
            int arr = id >> 10;                      // 0 Kh, 1 Kl, 2 Vh, 3 Vl
            int rc  = id & 1023;
            int row = rc >> 4;
            int c   = rc & 15;
            const uint16_t *base =
                (arr == 0) ? Khg : (arr == 1) ? Klg : (arr == 2) ? Vhg : Vlg;
            cpa16(stb + ((arr * FL_AU + row * 68 + c * 4) << 2),
                  base + (size_t)(kv0 + row) * DHEAD + c * 8);
        }
    };

    float Oacc[16][4];
#pragma unroll
    for (int i = 0; i < 16; i++)
#pragma unroll
        for (int e = 0; e < 4; e++) Oacc[i][e] = 0.f;
    float m_i[2] = {-1e30f, -1e30f};
    float l_i[2] = {0.f, 0.f};

    const int wr0   = warp * 16;
    const int grow0 = qr0 + wr0;
    const int jmax  = 2 * qt + 1;

    copy_kv(0, 0);
    CP_COMMIT();

    const int lt = lane >> 3;      // tile index within x4 (0..3)
    const int lr = lane & 7;       // row within tile

    for (int j = 0; j <= jmax; j++) {
        const int kv0 = j * 64;
        CP_WAIT0();
        __syncthreads();
        if (j + 1 <= jmax) {
            copy_kv((j + 1) * 64, (j + 1) & 1);
            CP_COMMIT();
        }

        if (kv0 <= grow0 + 15) {
            const uint32_t QH = sbase;
            const uint32_t KH = sbase + ((2 * FL_QU + (j & 1) * FL_STGU) << 2);
            const uint32_t VH = KH + ((2 * FL_AU) << 2);

            // ---- S = Q @ K^T : 16 x 64 per warp ----
            float sacc[8][4];
#pragma unroll
            for (int nt = 0; nt < 8; nt++)
#pragma unroll
                for (int e = 0; e < 4; e++) sacc[nt][e] = 0.f;

#pragma unroll
            for (int kk = 0; kk < 8; kk++) {
                // Q A-fragments: tiles (rows wr0+{0,8}, kchunk kk*2+{0,1})
                uint32_t ah[4], al[4];
                {
                    uint32_t qrow = wr0 + ((lt & 1) << 3) + lr;
                    uint32_t qc   = (kk << 1) + (lt >> 1);
                    uint32_t qa   = QH + ((qrow * 68 + qc * 4) << 2);
                    LDSM4(ah, qa);
                    LDSM4(al, qa + (FL_QU << 2));
                }
#pragma unroll
                for (int i = 0; i < 4; i++) {
                    // K B-fragments: tiles (n 16i+{0,8}+lr, kchunk kk*2+{0,1})
                    uint32_t krow = (i << 4) + ((lt >> 1) << 3) + lr;
                    uint32_t kc   = (kk << 1) + (lt & 1);
                    uint32_t ka   = KH + ((krow * 68 + kc * 4) << 2);
                    uint32_t bh[4], bl[4];
                    LDSM4(bh, ka);
                    LDSM4(bl, ka + (FL_AU << 2));
                    mma3(sacc[2 * i],     ah, al, bh[0], bh[1], bl[0], bl[1]);
                    mma3(sacc[2 * i + 1], ah, al, bh[2], bh[3], bl[2], bl[3]);
                }
            }

            // ---- causal mask (near diagonal only) ----
            if (kv0 + 63 > grow0) {
                const int r0 = grow0 + g;
#pragma unroll
                for (int nt = 0; nt < 8; nt++) {
                    int c0 = kv0 + nt * 8 + (q4 << 1);
                    if (c0 > r0)         sacc[nt][0] = -1e30f;
                    if (c0 + 1 > r0)     sacc[nt][1] = -1e30f;
                    if (c0 > r0 + 8)     sacc[nt][2] = -1e30f;
                    if (c0 + 1 > r0 + 8) sacc[nt][3] = -1e30f;
                }
            }

            // ---- streaming softmax ----
            float rmax0 = -1e30f, rmax1 = -1e30f;
#pragma unroll
            for (int nt = 0; nt < 8; nt++) {
                rmax0 = fmaxf(rmax0, fmaxf(sacc[nt][0], sacc[nt][1]));
                rmax1 = fmaxf(rmax1, fmaxf(sacc[nt][2], sacc[nt][3]));
            }
            rmax0 = fmaxf(rmax0, __shfl_xor_sync(0xffffffffu, rmax0, 1));
            rmax0 = fmaxf(rmax0, __shfl_xor_sync(0xffffffffu, rmax0, 2));
            rmax1 = fmaxf(rmax1, __shfl_xor_sync(0xffffffffu, rmax1, 1));
            rmax1 = fmaxf(rmax1, __shfl_xor_sync(0xffffffffu, rmax1, 2));

            float mn0 = fmaxf(m_i[0], rmax0);
            float mn1 = fmaxf(m_i[1], rmax1);
            float alpha0 = __expf(m_i[0] - mn0);
            float alpha1 = __expf(m_i[1] - mn1);

            float rs0 = 0.f, rs1 = 0.f;
#pragma unroll
            for (int nt = 0; nt < 8; nt++) {
                sacc[nt][0] = __expf(sacc[nt][0] - mn0);
                sacc[nt][1] = __expf(sacc[nt][1] - mn0);
                sacc[nt][2] = __expf(sacc[nt][2] - mn1);
                sacc[nt][3] = __expf(sacc[nt][3] - mn1);
                rs0 += sacc[nt][0] + sacc[nt][1];
                rs1 += sacc[nt][2] + sacc[nt][3];
            }
            rs0 += __shfl_xor_sync(0xffffffffu, rs0, 1);
            rs0 += __shfl_xor_sync(0xffffffffu, rs0, 2);
            rs1 += __shfl_xor_sync(0xffffffffu, rs1, 1);
            rs1 += __shfl_xor_sync(0xffffffffu, rs1, 2);

            l_i[0] = l_i[0] * alpha0 + rs0;
            l_i[1] = l_i[1] * alpha1 + rs1;
            m_i[0] = mn0;
            m_i[1] = mn1;

#pragma unroll
            for (int nt = 0; nt < 16; nt++) {
                Oacc[nt][0] *= alpha0; Oacc[nt][1] *= alpha0;
                Oacc[nt][2] *= alpha1; Oacc[nt][3] *= alpha1;
            }

            // ---- O += P @ V (P in regs; V frags via trans ldmatrix) ----
#pragma unroll
            for (int c = 0; c < 4; c++) {
                uint32_t ph[4], pl[4];
                split_pack(sacc[2 * c][0],     sacc[2 * c][1],     ph[0], pl[0]);
                split_pack(sacc[2 * c][2],     sacc[2 * c][3],     ph[1], pl[1]);
                split_pack(sacc[2 * c + 1][0], sacc[2 * c + 1][1], ph[2], pl[2]);
                split_pack(sacc[2 * c + 1][2], sacc[2 * c + 1][3], ph[3], pl[3]);
#pragma unroll
                for (int i = 0; i < 8; i++) {
                    // V tiles: (s rows c*16+{0,8}+lr, dchunk 2i+{0,1}), trans
                    uint32_t srow = (c << 4) + ((lt & 1) << 3) + lr;
                    uint32_t dc   = (i << 1) + (lt >> 1);
                    uint32_t va   = VH + ((srow * 68 + dc * 4) << 2);
                    uint32_t vh[4], vl[4];
                    LDSM4T(vh, va);
                    LDSM4T(vl, va + (FL_AU << 2));
                    mma3(Oacc[2 * i],     ph, pl, vh[0], vh[1], vl[0], vl[1]);
                    mma3(Oacc[2 * i + 1], ph, pl, vh[2], vh[3], vl[2], vl[3]);
                }
            }
        }
        __syncthreads();
    }

    // ---- epilogue: normalize, split, write hi/lo attn ----
    const float inv0 = 1.f / l_i[0];
    const float inv1 = 1.f / l_i[1];
    const int   s0   = qr0 + wr0 + g;
    const size_t base0 = ((size_t)(b * SEQ) + s0) * (HID / 2) + h * 64;
#pragma unroll
    for (int nt = 0; nt < 16; nt++) {
        float o00 = Oacc[nt][0] * inv0, o01 = Oacc[nt][1] * inv0;
        float o10 = Oacc[nt][2] * inv1, o11 = Oacc[nt][3] * inv1;
        uint32_t h0, l0, h1, l1;
        split_pack(o00, o01, h0, l0);
        split_pack(o10, o11, h1, l1);
        size_t ci = base0 + nt * 4 + q4;
        ((uint32_t *)g_ath)[ci] = h0;
        ((uint32_t *)g_atl)[ci] = l0;
        ((uint32_t *)g_ath)[ci + 8 * (HID / 2)] = h1;
        ((uint32_t *)g_atl)[ci + 8 * (HID / 2)] = l1;
    }
}

// ---------------------------------------------------------------------------
// kernel_launch
// ---------------------------------------------------------------------------
extern "C" void kernel_launch(void *const *d_in, const int *in_sizes, int n_in,
                              void *d_out, int out_size) {
    (void)in_sizes; (void)n_in; (void)out_size;
    const float *hs     = (const float *)d_in[0];
    const float *w_attn = (const float *)d_in[1];
    const float *b_attn = (const float *)d_in[2];
    const float *w_proj = (const float *)d_in[3];
    const float *b_proj = (const float *)d_in[4];
    float *out = (float *)d_out;

    cudaFuncSetAttribute(gemm_ldsm<1>,
                         cudaFuncAttributeMaxDynamicSharedMemorySize, GEMM_SMEM);
    cudaFuncSetAttribute(gemm_ldsm<0>,
                         cudaFuncAttributeMaxDynamicSharedMemorySize, GEMM_SMEM);
    cudaFuncSetAttribute(flash_causal,
                         cudaFuncAttributeMaxDynamicSharedMemorySize, FLASH_SMEM);

    uint16_t *hidh, *hidl, *wah, *wal, *wph, *wpl, *ath, *atl;
    cudaGetSymbolAddress((void **)&hidh, g_hidh);
    cudaGetSymbolAddress((void **)&hidl, g_hidl);
    cudaGetSymbolAddress((void **)&wah,  g_wah);
    cudaGetSymbolAddress((void **)&wal,  g_wal);
    cudaGetSymbolAddress((void **)&wph,  g_wph);
    cudaGetSymbolAddress((void **)&wpl,  g_wpl);
    cudaGetSymbolAddress((void **)&ath,  g_ath);
    cudaGetSymbolAddress((void **)&atl,  g_atl);

    // 0) pre-split fp32 inputs to bf16 hi/lo
    split4<<<(MTOT * HID) / 1024, 256>>>((const float4 *)hs,
                                         (uint2 *)hidh, (uint2 *)hidl);
    split4<<<(HID * NQKV) / 1024, 256>>>((const float4 *)w_attn,
                                         (uint2 *)wah, (uint2 *)wal);
    split4<<<(HID * HID) / 1024, 256>>>((const float4 *)w_proj,
                                        (uint2 *)wph, (uint2 *)wpl);

    // 1) QKV projection -> split bf16 q/k/v (Q pre-scaled)
    gemm_ldsm<1><<<dim3(NQKV / 256, MTOT / 128), 256, GEMM_SMEM>>>(
        hidh, hidl, wah, wal, b_attn, nullptr, MTOT, NQKV, HID);

    // 2) causal flash attention -> split bf16 attn (g_ath/g_atl)
    flash_causal<<<dim3(SEQ / 128, NHEAD, BB), 256, FLASH_SMEM>>>();

    // 3) output projection -> d_out
    gemm_ldsm<0><<<dim3(HID / 256, MTOT / 128), 256, GEMM_SMEM>>>(
        ath, atl, wph, wpl, b_proj, out, MTOT, HID, HID);
}